// round 15
// baseline (speedup 1.0000x reference)
#include <cuda_runtime.h>
#include <cuda_fp16.h>
#include <math.h>
#include <stdint.h>

// ---------------- problem constants ----------------
#define BB 128      // batch
#define NN 49       // spatial tokens
#define CIN 2048
#define GG 256      // query groups
#define DD 768      // model dim
#define HH 8        // heads
#define HD 96       // head dim
#define FF 2048
#define NCLS 12547
#define DUP 50
#define DKV 1536    // concat K|V projection width
#define NGRP 251    // groups that actually reach the 12547-class output

// ---------------- asm helpers (sm_80+ features only) -------------------------
__device__ __forceinline__ uint32_t smem_u32(const void* p) {
    uint32_t a;
    asm("{ .reg .u64 t; cvta.to.shared.u64 t, %1; cvt.u32.u64 %0, t; }" : "=r"(a) : "l"(p));
    return a;
}
#define CP16(dst, src) \
    asm volatile("cp.async.cg.shared.global [%0], [%1], 16;" :: "r"(dst), "l"(src))
#define CP_COMMIT() asm volatile("cp.async.commit_group;" ::: "memory")
#define CP_WAIT(n)  asm volatile("cp.async.wait_group %0;" :: "n"(n) : "memory")
#define LDSM4(r, addr) \
    asm volatile("ldmatrix.sync.aligned.m8n8.x4.shared.b16 {%0,%1,%2,%3}, [%4];" \
                 : "=r"((r)[0]), "=r"((r)[1]), "=r"((r)[2]), "=r"((r)[3]) : "r"(addr))
#define MMA_F16(c, a, b0, b1) \
    asm volatile("mma.sync.aligned.m16n8k16.row.col.f32.f16.f16.f32 " \
                 "{%0,%1,%2,%3},{%4,%5,%6,%7},{%8,%9},{%0,%1,%2,%3};" \
                 : "+f"((c)[0]), "+f"((c)[1]), "+f"((c)[2]), "+f"((c)[3]) \
                 : "r"((a)[0]), "r"((a)[1]), "r"((a)[2]), "r"((a)[3]), "r"(b0), "r"(b1))

// ---------------- scratch (device globals) -----------------------------------
// fp32
__device__ float g_t1   [GG * DD];
__device__ float g_q    [GG * DD];
__device__ float g_bkv  [DKV];            // concat bias bk|bv
// fp16 activation operands
__device__ __half g_xh [BB * NN * CIN];
__device__ __half g_mh [BB * NN * DD];
__device__ __half g_t1h[GG * DD];
__device__ __half g_kvh[BB * NN * DKV];   // concat K|V (fp16)
__device__ __half g_aoh[BB * GG * DD];
__device__ __half g_oph[BB * GG * DD];    // Wo out (fp16)
__device__ __half g_t2h[BB * GG * DD];
__device__ __half g_ffh[BB * GG * FF];
__device__ __half g_f2h[BB * GG * DD];    // W2 out (fp16)
__device__ __half g_hh [BB * GG * DD];    // final LN out (fp16, groupfc input)
// transposed fp16 weights: [N,K]
__device__ __half tWe [DD * CIN];
__device__ __half tWq [DD * DD];
__device__ __half tWkv[DKV * DD];         // rows 0..767 = Wk^T, 768..1535 = Wv^T
__device__ __half tWo [DD * DD];
__device__ __half tW1 [FF * DD];
__device__ __half tW2 [DD * FF];
__device__ __half tWg [GG * 64 * DD];     // per-group [64(f,pad), 768(d)] fp16

// ---------------- weight transpose: W[K,N] fp32 -> [N,K] fp16 ----------------
__global__ __launch_bounds__(256)
void transpose_half(const float* __restrict__ W, __half* __restrict__ o,
                    int K, int N)
{
    __shared__ float tile[32][33];
    const int tx = threadIdx.x & 31, ty = threadIdx.x >> 5;
    const int kb = blockIdx.y * 32, nb = blockIdx.x * 32;
    #pragma unroll
    for (int i = 0; i < 4; i++)
        tile[ty + i * 8][tx] = W[(size_t)(kb + ty + i * 8) * N + nb + tx];
    __syncthreads();
    #pragma unroll
    for (int i = 0; i < 4; i++) {
        const int n = nb + ty + i * 8, k = kb + tx;
        o[(size_t)n * K + k] = __float2half(tile[tx][ty + i * 8]);
    }
}

// ---------------- batched 768x768 transpose (4 matrices in one launch) --------
__global__ __launch_bounds__(256)
void transpose4_half(const float* __restrict__ s0, __half* __restrict__ d0,
                     const float* __restrict__ s1, __half* __restrict__ d1,
                     const float* __restrict__ s2, __half* __restrict__ d2,
                     const float* __restrict__ s3, __half* __restrict__ d3)
{
    const float* W;
    __half* o;
    switch (blockIdx.z) {
        case 0: W = s0; o = d0; break;
        case 1: W = s1; o = d1; break;
        case 2: W = s2; o = d2; break;
        default: W = s3; o = d3; break;
    }
    __shared__ float tile[32][33];
    const int tx = threadIdx.x & 31, ty = threadIdx.x >> 5;
    const int kb = blockIdx.y * 32, nb = blockIdx.x * 32;
    #pragma unroll
    for (int i = 0; i < 4; i++)
        tile[ty + i * 8][tx] = W[(size_t)(kb + ty + i * 8) * DD + nb + tx];
    __syncthreads();
    #pragma unroll
    for (int i = 0; i < 4; i++) {
        const int n = nb + ty + i * 8, k = kb + tx;
        o[(size_t)n * DD + k] = __float2half(tile[tx][ty + i * 8]);
    }
}

// ---------------- Wg transpose: [G,768,50] fp32 -> [G,64,768] fp16 ------------
__global__ __launch_bounds__(256)
void transpose_wg(const float* __restrict__ Wg, __half* __restrict__ o)
{
    __shared__ float t[128 * DUP];
    const int g = blockIdx.x, dc = blockIdx.y;
    const int tid = threadIdx.x;
    for (int i = tid; i < 128 * DUP; i += 256)
        t[i] = Wg[(size_t)g * DD * DUP + dc * 128 * DUP + i];
    __syncthreads();
    for (int j = tid; j < 64 * 128; j += 256) {
        const int f = j >> 7, d = j & 127;
        const float v = (f < DUP) ? t[d * DUP + f] : 0.f;
        o[(size_t)g * 64 * DD + (size_t)f * DD + dc * 128 + d] = __float2half(v);
    }
}

// ---------------- elementwise fp32 -> fp16 (for x) ---------------------------
__global__ __launch_bounds__(256)
void convert_half(const float* __restrict__ in, __half* __restrict__ out)
{
    const int i = (blockIdx.x * 256 + threadIdx.x) * 4;
    float4 v = *reinterpret_cast<const float4*>(in + i);
    __half2 a(__float2half(v.x), __float2half(v.y));
    __half2 b(__float2half(v.z), __float2half(v.w));
    *reinterpret_cast<__half2*>(out + i)     = a;
    *reinterpret_cast<__half2*>(out + i + 2) = b;
}

// ---------------- concat bk|bv ------------------------------------------------
__global__ void concat_bias(const float* __restrict__ bk, const float* __restrict__ bv,
                            float* __restrict__ o)
{
    const int i = blockIdx.x * 256 + threadIdx.x;
    if (i < DD) o[i] = bk[i];
    else if (i < DKV) o[i] = bv[i - DD];
}

// ---------------- fp16 single-pass tensor-core GEMM (BK=64) ------------------
// C = act(alpha*(A @ B^T + bias));  A [M,K] fp16, B [N,K] fp16.
// BM=BN=128, BK=64; 4 warps x (64x64); double-buffered; 1 sync / 64-K.
// M%128==0, N%128==0, K%64==0.
#define LD64 72                      // smem row stride in halves (144B, conflict-free)
#define T64_B (128 * LD64 * 2)       // 18432B per tile
#define S64_B (2 * T64_B)            // 36864B per stage (A, B)
#define GEMM_SMEM (2 * S64_B)        // 73728B

template <int RELU, int HOUT>
__global__ __launch_bounds__(128, 2)
void tc_gemm(const __half* __restrict__ A, const __half* __restrict__ B,
             const float* __restrict__ bias,
             float* __restrict__ Cf, __half* __restrict__ Ch,
             int M, int N, int K, float alpha)
{
    extern __shared__ __half sm[];
    const uint32_t sb = smem_u32(sm);
    const int tid = threadIdx.x, wid = tid >> 5, lane = tid & 31;
    const int wm = wid & 1, wn = wid >> 1;
    const int m0 = blockIdx.y * 128, n0 = blockIdx.x * 128;
    const int nst = K >> 6;

    // 16 x 16B chunks per thread per stage (A 8, B 8)
    auto load_stage = [&](int s, int buf) {
        const int k0 = s << 6;
        const uint32_t d0 = sb + buf * S64_B;
        #pragma unroll
        for (int i = 0; i < 16; i++) {
            const int isA = (i < 8);
            const int c = (i & 7) * 128 + tid;        // 0..1023 within tile
            const int row = c >> 3, part = c & 7;
            const __half* src = (isA ? A + (size_t)(m0 + row) * K
                                     : B + (size_t)(n0 + row) * K) + k0 + part * 8;
            const uint32_t dst = d0 + (isA ? 0 : T64_B) + row * (LD64 * 2) + part * 16;
            CP16(dst, src);
        }
        CP_COMMIT();
    };

    float acc[4][8][4];
    #pragma unroll
    for (int i = 0; i < 4; i++)
        #pragma unroll
        for (int j = 0; j < 8; j++)
            #pragma unroll
            for (int q = 0; q < 4; q++) acc[i][j][q] = 0.f;

    load_stage(0, 0);

    const int a_r = (lane & 15), a_c8 = (lane >> 4) * 8;
    const int b_r = ((lane >> 4) & 1) * 8 + (lane & 7);
    const int b_c8 = ((lane >> 3) & 1) * 8;

    #pragma unroll 1
    for (int s = 0; s < nst; s++) {
        CP_WAIT(0);                    // stage s resident
        __syncthreads();               // also fences buffer reuse (compute s-1 done)
        if (s + 1 < nst) load_stage(s + 1, (s + 1) & 1);

        const uint32_t ab = sb + (s & 1) * S64_B;
        const uint32_t bb = ab + T64_B;

        #pragma unroll
        for (int ks = 0; ks < 4; ks++) {
            const int kh = ks * 16;
            uint32_t fA[4][4], fB[4][4];
            #pragma unroll
            for (int i = 0; i < 4; i++) {
                const uint32_t off = ((wm * 64 + i * 16 + a_r) * LD64 + kh + a_c8) * 2;
                LDSM4(fA[i], ab + off);
            }
            #pragma unroll
            for (int j = 0; j < 4; j++) {
                const uint32_t off = ((wn * 64 + j * 16 + b_r) * LD64 + kh + b_c8) * 2;
                LDSM4(fB[j], bb + off);
            }
            #pragma unroll
            for (int n = 0; n < 8; n++) {
                const int j = n >> 1, h = (n & 1) * 2;
                const uint32_t b0 = fB[j][h], b1 = fB[j][h + 1];
                #pragma unroll
                for (int i = 0; i < 4; i++)
                    MMA_F16(acc[i][n], fA[i], b0, b1);
            }
        }
    }

    // ---- epilogue ----
    const int row0 = m0 + wm * 64 + (lane >> 2);
    const int col0 = n0 + wn * 64 + (lane & 3) * 2;
    #pragma unroll
    for (int i = 0; i < 4; i++) {
        #pragma unroll
        for (int j = 0; j < 8; j++) {
            const int r = row0 + i * 16;
            const int c = col0 + j * 8;
            const float b0 = bias[c], b1 = bias[c + 1];
            float v0 = alpha * (acc[i][j][0] + b0);
            float v1 = alpha * (acc[i][j][1] + b1);
            float v2 = alpha * (acc[i][j][2] + b0);
            float v3 = alpha * (acc[i][j][3] + b1);
            if (RELU) {
                v0 = fmaxf(v0, 0.f); v1 = fmaxf(v1, 0.f);
                v2 = fmaxf(v2, 0.f); v3 = fmaxf(v3, 0.f);
            }
            if (!HOUT) {
                *reinterpret_cast<float2*>(Cf + (size_t)r * N + c)       = make_float2(v0, v1);
                *reinterpret_cast<float2*>(Cf + (size_t)(r + 8) * N + c) = make_float2(v2, v3);
            } else {
                *reinterpret_cast<__half2*>(Ch + (size_t)r * N + c) =
                    __half2(__float2half(v0), __float2half(v1));
                *reinterpret_cast<__half2*>(Ch + (size_t)(r + 8) * N + c) =
                    __half2(__float2half(v2), __float2half(v3));
            }
        }
    }
}

// ---------------- LayerNorm over D=768 ---------------------------------------
// mode 0: x = 2*a32[row]
// mode 1: x = a16[row] + r32[row%G]
// mode 2: x = a16[row] + r16[row]
__global__ __launch_bounds__(256)
void ln_kernel(const float* __restrict__ a32, const __half* __restrict__ a16,
               const float* __restrict__ r32, const __half* __restrict__ r16,
               const float* __restrict__ gamma, const float* __restrict__ beta,
               float* __restrict__ out, __half* __restrict__ oh, int mode)
{
    const int row = blockIdx.x;
    const int t = threadIdx.x;

    float x[3];
    #pragma unroll
    for (int j = 0; j < 3; j++) {
        const int idx = t + j * 256;
        float val;
        if (mode == 0) {
            val = 2.f * a32[(size_t)row * DD + idx];
        } else {
            val = __half2float(a16[(size_t)row * DD + idx]);
            if (mode == 1) val += r32[(size_t)(row & (GG - 1)) * DD + idx];
            else           val += __half2float(r16[(size_t)row * DD + idx]);
        }
        x[j] = val;
    }
    float s1 = x[0] + x[1] + x[2];
    float s2 = x[0] * x[0] + x[1] * x[1] + x[2] * x[2];
    #pragma unroll
    for (int off = 16; off; off >>= 1) {
        s1 += __shfl_xor_sync(0xffffffffu, s1, off);
        s2 += __shfl_xor_sync(0xffffffffu, s2, off);
    }
    __shared__ float sh1[8], sh2[8];
    const int w = t >> 5, lane = t & 31;
    if (lane == 0) { sh1[w] = s1; sh2[w] = s2; }
    __syncthreads();
    float S1 = 0.f, S2 = 0.f;
    #pragma unroll
    for (int i = 0; i < 8; i++) { S1 += sh1[i]; S2 += sh2[i]; }
    const float mean = S1 * (1.f / (float)DD);
    const float var  = S2 * (1.f / (float)DD) - mean * mean;
    const float rstd = rsqrtf(var + 1e-5f);

    #pragma unroll
    for (int j = 0; j < 3; j++) {
        const int idx = t + j * 256;
        const float v = (x[j] - mean) * rstd * gamma[idx] + beta[idx];
        if (out) out[(size_t)row * DD + idx] = v;
        if (oh) oh[(size_t)row * DD + idx] = __float2half(v);
    }
}

// ---------------- fused cross-attention (fp16 kv concat), fp16 output --------
__global__ __launch_bounds__(256)
void attn_kernel(const float* __restrict__ q, const __half* __restrict__ kv,
                 __half* __restrict__ oh)
{
    __shared__ float ks[NN][HD];
    __shared__ float vs[NN][HD];
    const int h = blockIdx.x, b = blockIdx.y;
    const int t = threadIdx.x;

    for (int i = t; i < NN * HD; i += 256) {
        const int n = i / HD, d = i % HD;
        const size_t gi = ((size_t)(b * NN + n)) * DKV + h * HD + d;
        ks[n][d] = __half2float(kv[gi]);
        vs[n][d] = __half2float(kv[gi + DD]);
    }
    __syncthreads();

    const int g = t;
    float4 qv[HD / 4];
    const float4* qp = reinterpret_cast<const float4*>(q + (size_t)g * DD + h * HD);
    #pragma unroll
    for (int i = 0; i < HD / 4; i++) qv[i] = qp[i];

    float s[NN];
    #pragma unroll 7
    for (int n = 0; n < NN; n++) {
        const float4* kp = reinterpret_cast<const float4*>(ks[n]);
        float acc = 0.f;
        #pragma unroll
        for (int i = 0; i < HD / 4; i++) {
            float4 kk = kp[i];
            acc += qv[i].x * kk.x + qv[i].y * kk.y + qv[i].z * kk.z + qv[i].w * kk.w;
        }
        s[n] = acc;
    }
    float m = -1e30f;
    #pragma unroll
    for (int n = 0; n < NN; n++) m = fmaxf(m, s[n]);
    float sum = 0.f;
    #pragma unroll
    for (int n = 0; n < NN; n++) { s[n] = __expf(s[n] - m); sum += s[n]; }
    const float inv = 1.f / sum;

    const size_t ob = ((size_t)(b * GG + g)) * DD + h * HD;
    #pragma unroll
    for (int d4 = 0; d4 < HD / 4; d4++) {
        float4 acc = {0.f, 0.f, 0.f, 0.f};
        #pragma unroll 7
        for (int n = 0; n < NN; n++) {
            const float p = s[n];
            float4 vv = *reinterpret_cast<const float4*>(&vs[n][d4 * 4]);
            acc.x += p * vv.x; acc.y += p * vv.y; acc.z += p * vv.z; acc.w += p * vv.w;
        }
        acc.x *= inv; acc.y *= inv; acc.z *= inv; acc.w *= inv;
        *reinterpret_cast<__half2*>(oh + ob + d4 * 4) =
            __half2(__float2half(acc.x), __float2half(acc.y));
        *reinterpret_cast<__half2*>(oh + ob + d4 * 4 + 2) =
            __half2(__float2half(acc.z), __float2half(acc.w));
    }
}

// ---------------- GroupFC on tensor cores ------------------------------------
#define LDSH 40
#define GF_A_B (128 * LDSH * 2)          // 10240B
#define GF_B_B (64 * LDSH * 2)           // 5120B
#define GF_STAGE (GF_A_B + GF_B_B)       // 15360B
#define GF_SMEM (2 * GF_STAGE)           // 30720B

__global__ __launch_bounds__(128, 2)
void groupfc_tc(const __half* __restrict__ h, const __half* __restrict__ Wt,
                const float* __restrict__ bg, float* __restrict__ out)
{
    extern __shared__ __half sm[];
    const uint32_t sb = smem_u32(sm);
    const int g = blockIdx.x;
    const int tid = threadIdx.x, wid = tid >> 5, lane = tid & 31;

    auto load_stage = [&](int s, int buf) {
        const int k0 = s << 5;
        const uint32_t d0 = sb + buf * GF_STAGE;
        #pragma unroll
        for (int i = 0; i < 4; i++) {
            const int c = i * 128 + tid;
            const int row = c >> 2, part = c & 3;
            const __half* src = h + ((size_t)(row * GG + g)) * DD + k0 + part * 8;
            CP16(d0 + row * (LDSH * 2) + part * 16, src);
        }
        #pragma unroll
        for (int i = 0; i < 2; i++) {
            const int c = i * 128 + tid;
            const int row = c >> 2, part = c & 3;
            const __half* src = Wt + (size_t)g * 64 * DD + (size_t)row * DD + k0 + part * 8;
            CP16(d0 + GF_A_B + row * (LDSH * 2) + part * 16, src);
        }
        CP_COMMIT();
    };

    float acc[2][8][4];
    #pragma unroll
    for (int i = 0; i < 2; i++)
        #pragma unroll
        for (int j = 0; j < 8; j++)
            #pragma unroll
            for (int q = 0; q < 4; q++) acc[i][j][q] = 0.f;

    load_stage(0, 0);

    const int a_r = (lane & 15), a_c8 = (lane >> 4) * 8;
    const int b_r = ((lane >> 4) & 1) * 8 + (lane & 7);
    const int b_c8 = ((lane >> 3) & 1) * 8;
    const int nst = DD >> 5;

    #pragma unroll 1
    for (int s = 0; s < nst; s++) {
        if (s + 1 < nst) load_stage(s + 1, (s + 1) & 1); else CP_COMMIT();
        CP_WAIT(1);
        __syncthreads();
        const uint32_t ab = sb + (s & 1) * GF_STAGE;
        const uint32_t bb = ab + GF_A_B;

        #pragma unroll
        for (int ks = 0; ks < 2; ks++) {
            const int kh = ks * 16;
            uint32_t fA[2][4], fB[4][4];
            #pragma unroll
            for (int i = 0; i < 2; i++) {
                const uint32_t off = ((wid * 32 + i * 16 + a_r) * LDSH + kh + a_c8) * 2;
                LDSM4(fA[i], ab + off);
            }
            #pragma unroll
            for (int j = 0; j < 4; j++) {
                const uint32_t off = ((j * 16 + b_r) * LDSH + kh + b_c8) * 2;
                LDSM4(fB[j], bb + off);
            }
            #pragma unroll
            for (int n = 0; n < 8; n++) {
                const int j = n >> 1, hh = (n & 1) * 2;
                const uint32_t b0 = fB[j][hh], b1 = fB[j][hh + 1];
                #pragma unroll
                for (int i = 0; i < 2; i++)
                    MMA_F16(acc[i][n], fA[i], b0, b1);
            }
        }
        __syncthreads();
    }

    const int row0 = wid * 32 + (lane >> 2);
    const int col0 = (lane & 3) * 2;
    #pragma unroll
    for (int i = 0; i < 2; i++) {
        #pragma unroll
        for (int j = 0; j < 8; j++) {
            const int r0 = row0 + i * 16;
            const int f0 = col0 + j * 8;
            #pragma unroll
            for (int e = 0; e < 2; e++) {
                const int f = f0 + e;
                const int c = g * DUP + f;
                if (f < DUP && c < NCLS) {
                    out[(size_t)r0 * NCLS + c]       = acc[i][j][0 + e] + bg[c];
                    out[(size_t)(r0 + 8) * NCLS + c] = acc[i][j][2 + e] + bg[c];
                }
            }
        }
    }
}

// ---------------- launch -----------------------------------------------------
static float* sym(const void* s) { void* p = nullptr; cudaGetSymbolAddress(&p, s); return (float*)p; }
static __half* symh(const void* s) { void* p = nullptr; cudaGetSymbolAddress(&p, s); return (__half*)p; }

extern "C" void kernel_launch(void* const* d_in, const int* in_sizes, int n_in,
                              void* d_out, int out_size)
{
    (void)in_sizes; (void)n_in; (void)out_size;
    const float* x      = (const float*)d_in[0];
    const float* We     = (const float*)d_in[1];
    const float* be     = (const float*)d_in[2];
    const float* query  = (const float*)d_in[3];
    const float* Wq     = (const float*)d_in[4];
    const float* bq     = (const float*)d_in[5];
    const float* Wk     = (const float*)d_in[6];
    const float* bk     = (const float*)d_in[7];
    const float* Wv     = (const float*)d_in[8];
    const float* bv     = (const float*)d_in[9];
    const float* Wo     = (const float*)d_in[10];
    const float* bo     = (const float*)d_in[11];
    const float* g1     = (const float*)d_in[12];
    const float* beta1  = (const float*)d_in[13];
    const float* g2     = (const float*)d_in[14];
    const float* beta2  = (const float*)d_in[15];
    const float* g3     = (const float*)d_in[16];
    const float* beta3  = (const float*)d_in[17];
    const float* W1     = (const float*)d_in[18];
    const float* b1     = (const float*)d_in[19];
    const float* W2     = (const float*)d_in[20];
    const float* b2     = (const float*)d_in[21];
    const float* Wg     = (const float*)d_in[22];
    const float* bg     = (const float*)d_in[23];
    float* out = (float*)d_out;

    float *p_t1 = sym(g_t1), *p_q = sym(g_q), *p_bkv = sym(g_bkv);
    __half *p_xh = symh(g_xh), *p_mh = symh(g_mh), *p_t1h = symh(g_t1h);
    __half *p_kvh = symh(g_kvh), *p_aoh = symh(g_aoh), *p_oph = symh(g_oph);
    __half *p_t2h = symh(g_t2h), *p_ffh = symh(g_ffh), *p_f2h = symh(g_f2h);
    __half *p_hh = symh(g_hh);
    __half *pWe = symh(tWe), *pWq = symh(tWq), *pWkv = symh(tWkv);
    __half *pWo = symh(tWo), *pW1 = symh(tW1), *pW2 = symh(tW2), *pWg = symh(tWg);

    cudaFuncSetAttribute(tc_gemm<0, 0>, cudaFuncAttributeMaxDynamicSharedMemorySize, GEMM_SMEM);
    cudaFuncSetAttribute(tc_gemm<0, 1>, cudaFuncAttributeMaxDynamicSharedMemorySize, GEMM_SMEM);
    cudaFuncSetAttribute(tc_gemm<1, 1>, cudaFuncAttributeMaxDynamicSharedMemorySize, GEMM_SMEM);
    cudaFuncSetAttribute(groupfc_tc, cudaFuncAttributeMaxDynamicSharedMemorySize, GF_SMEM);

    const float qscale = 0.10206207261596577f;  // 1/sqrt(96)

    // prep: weight transposes (fp16 [N,K]), input convert, bias concat
    transpose_half<<<dim3(DD / 32, CIN / 32), 256>>>(We, pWe, CIN, DD);
    convert_half<<<(BB * NN * CIN) / 1024, 256>>>(x, p_xh);
    transpose4_half<<<dim3(DD / 32, DD / 32, 4), 256>>>(
        Wq, pWq, Wk, pWkv, Wv, pWkv + (size_t)DD * DD, Wo, pWo);
    concat_bias<<<(DKV + 255) / 256, 256>>>(bk, bv, p_bkv);
    transpose_half<<<dim3(FF / 32, DD / 32), 256>>>(W1, pW1, DD, FF);
    transpose_half<<<dim3(DD / 32, FF / 32), 256>>>(W2, pW2, FF, DD);
    transpose_wg<<<dim3(NGRP, DD / 128), 256>>>(Wg, pWg);

    // t1 = LN(2*query) (+fp16); q = (t1@Wq + bq)/sqrt(96)
    ln_kernel<<<GG, 256>>>(query, nullptr, nullptr, nullptr, g1, beta1, p_t1, p_t1h, 0);
    tc_gemm<0, 0><<<dim3(DD / 128, GG / 128), 128, GEMM_SMEM>>>(
        p_t1h, pWq, bq, p_q, nullptr, GG, DD, DD, qscale);

    // mem = relu(x @ We + be) -> fp16
    tc_gemm<1, 1><<<dim3(DD / 128, (BB * NN) / 128), 128, GEMM_SMEM>>>(
        p_xh, pWe, be, nullptr, p_mh, BB * NN, DD, CIN, 1.f);
    // fused K|V projection -> fp16 concat
    tc_gemm<0, 1><<<dim3(DKV / 128, (BB * NN) / 128), 128, GEMM_SMEM>>>(
        p_mh, pWkv, p_bkv, nullptr, p_kvh, BB * NN, DKV, DD, 1.f);

    // fused attention -> fp16
    attn_kernel<<<dim3(HH, BB), 256>>>(p_q, p_kvh, p_aoh);

    // output projection (fp16) + residual LN -> t2h (fp16 only)
    tc_gemm<0, 1><<<dim3(DD / 128, (BB * GG) / 128), 128, GEMM_SMEM>>>(
        p_aoh, pWo, bo, nullptr, p_oph, BB * GG, DD, DD, 1.f);
    ln_kernel<<<BB * GG, 256>>>(nullptr, p_oph, p_t1, nullptr, g2, beta2,
                                nullptr, p_t2h, 1);

    // FFN: ff = relu(t2@W1+b1) -> fp16; ffn2 = ff@W2+b2 -> fp16
    tc_gemm<1, 1><<<dim3(FF / 128, (BB * GG) / 128), 128, GEMM_SMEM>>>(
        p_t2h, pW1, b1, nullptr, p_ffh, BB * GG, FF, DD, 1.f);
    tc_gemm<0, 1><<<dim3(DD / 128, (BB * GG) / 128), 128, GEMM_SMEM>>>(
        p_ffh, pW2, b2, nullptr, p_f2h, BB * GG, DD, FF, 1.f);
    // h = LN(t2h + ffn2) -> fp16
    ln_kernel<<<BB * GG, 256>>>(nullptr, p_f2h, nullptr, p_t2h, g3, beta3,
                                nullptr, p_hh, 2);

    // GroupFC on tensor cores
    groupfc_tc<<<NGRP, 128, GF_SMEM>>>(p_hh, pWg, bg, out);
}

// round 16
// speedup vs baseline: 1.0327x; 1.0327x over previous
#include <cuda_runtime.h>
#include <cuda_fp16.h>
#include <math.h>
#include <stdint.h>

// ---------------- problem constants ----------------
#define BB 128      // batch
#define NN 49       // spatial tokens
#define CIN 2048
#define GG 256      // query groups
#define DD 768      // model dim
#define HH 8        // heads
#define HD 96       // head dim
#define FF 2048
#define NCLS 12547
#define DUP 50
#define DKV 1536    // concat K|V projection width
#define NGRP 251    // groups that actually reach the 12547-class output

// ---------------- asm helpers (sm_80+ features only) -------------------------
__device__ __forceinline__ uint32_t smem_u32(const void* p) {
    uint32_t a;
    asm("{ .reg .u64 t; cvta.to.shared.u64 t, %1; cvt.u32.u64 %0, t; }" : "=r"(a) : "l"(p));
    return a;
}
#define CP16(dst, src) \
    asm volatile("cp.async.cg.shared.global [%0], [%1], 16;" :: "r"(dst), "l"(src))
#define CP_COMMIT() asm volatile("cp.async.commit_group;" ::: "memory")
#define CP_WAIT(n)  asm volatile("cp.async.wait_group %0;" :: "n"(n) : "memory")
#define LDSM4(r, addr) \
    asm volatile("ldmatrix.sync.aligned.m8n8.x4.shared.b16 {%0,%1,%2,%3}, [%4];" \
                 : "=r"((r)[0]), "=r"((r)[1]), "=r"((r)[2]), "=r"((r)[3]) : "r"(addr))
#define MMA_F16(c, a, b0, b1) \
    asm volatile("mma.sync.aligned.m16n8k16.row.col.f32.f16.f16.f32 " \
                 "{%0,%1,%2,%3},{%4,%5,%6,%7},{%8,%9},{%0,%1,%2,%3};" \
                 : "+f"((c)[0]), "+f"((c)[1]), "+f"((c)[2]), "+f"((c)[3]) \
                 : "r"((a)[0]), "r"((a)[1]), "r"((a)[2]), "r"((a)[3]), "r"(b0), "r"(b1))

// ---------------- scratch (device globals) -----------------------------------
// fp32
__device__ float g_t1   [GG * DD];
__device__ float g_q    [GG * DD];
// fp16 activation operands
__device__ __half g_xh [BB * NN * CIN];
__device__ __half g_mh [BB * NN * DD];
__device__ __half g_t1h[GG * DD];
__device__ __half g_kvh[BB * NN * DKV];   // concat K|V (fp16)
__device__ __half g_aoh[BB * GG * DD];
__device__ __half g_oph[BB * GG * DD];    // Wo out (fp16)
__device__ __half g_t2h[BB * GG * DD];
__device__ __half g_ffh[BB * GG * FF];
__device__ __half g_f2h[BB * GG * DD];    // W2 out (fp16)
__device__ __half g_hh [BB * GG * DD];    // final LN out (fp16, groupfc input)
// transposed fp16 weights: [N,K]
__device__ __half tWe [DD * CIN];
__device__ __half tWq [DD * DD];
__device__ __half tWkv[DKV * DD];         // rows 0..767 = Wk^T, 768..1535 = Wv^T
__device__ __half tWo [DD * DD];
__device__ __half tW1 [FF * DD];
__device__ __half tW2 [DD * FF];
__device__ __half tWg [GG * 64 * DD];     // per-group [64(f,pad), 768(d)] fp16

// ---------------- weight transpose: W[K,N] fp32 -> [N,K] fp16 ----------------
__global__ __launch_bounds__(256)
void transpose_half(const float* __restrict__ W, __half* __restrict__ o,
                    int K, int N)
{
    __shared__ float tile[32][33];
    const int tx = threadIdx.x & 31, ty = threadIdx.x >> 5;
    const int kb = blockIdx.y * 32, nb = blockIdx.x * 32;
    #pragma unroll
    for (int i = 0; i < 4; i++)
        tile[ty + i * 8][tx] = W[(size_t)(kb + ty + i * 8) * N + nb + tx];
    __syncthreads();
    #pragma unroll
    for (int i = 0; i < 4; i++) {
        const int n = nb + ty + i * 8, k = kb + tx;
        o[(size_t)n * K + k] = __float2half(tile[tx][ty + i * 8]);
    }
}

// ---------------- batched 768x768 transpose (4 matrices in one launch) --------
__global__ __launch_bounds__(256)
void transpose4_half(const float* __restrict__ s0, __half* __restrict__ d0,
                     const float* __restrict__ s1, __half* __restrict__ d1,
                     const float* __restrict__ s2, __half* __restrict__ d2,
                     const float* __restrict__ s3, __half* __restrict__ d3)
{
    const float* W;
    __half* o;
    switch (blockIdx.z) {
        case 0: W = s0; o = d0; break;
        case 1: W = s1; o = d1; break;
        case 2: W = s2; o = d2; break;
        default: W = s3; o = d3; break;
    }
    __shared__ float tile[32][33];
    const int tx = threadIdx.x & 31, ty = threadIdx.x >> 5;
    const int kb = blockIdx.y * 32, nb = blockIdx.x * 32;
    #pragma unroll
    for (int i = 0; i < 4; i++)
        tile[ty + i * 8][tx] = W[(size_t)(kb + ty + i * 8) * DD + nb + tx];
    __syncthreads();
    #pragma unroll
    for (int i = 0; i < 4; i++) {
        const int n = nb + ty + i * 8, k = kb + tx;
        o[(size_t)n * DD + k] = __float2half(tile[tx][ty + i * 8]);
    }
}

// ---------------- Wg transpose: [G,768,50] fp32 -> [G,64,768] fp16 ------------
__global__ __launch_bounds__(256)
void transpose_wg(const float* __restrict__ Wg, __half* __restrict__ o)
{
    __shared__ float t[128 * DUP];
    const int g = blockIdx.x, dc = blockIdx.y;
    const int tid = threadIdx.x;
    for (int i = tid; i < 128 * DUP; i += 256)
        t[i] = Wg[(size_t)g * DD * DUP + dc * 128 * DUP + i];
    __syncthreads();
    for (int j = tid; j < 64 * 128; j += 256) {
        const int f = j >> 7, d = j & 127;
        const float v = (f < DUP) ? t[d * DUP + f] : 0.f;
        o[(size_t)g * 64 * DD + (size_t)f * DD + dc * 128 + d] = __float2half(v);
    }
}

// ---------------- elementwise fp32 -> fp16 (for x) ---------------------------
__global__ __launch_bounds__(256)
void convert_half(const float* __restrict__ in, __half* __restrict__ out)
{
    const int i = (blockIdx.x * 256 + threadIdx.x) * 4;
    float4 v = *reinterpret_cast<const float4*>(in + i);
    __half2 a(__float2half(v.x), __float2half(v.y));
    __half2 b(__float2half(v.z), __float2half(v.w));
    *reinterpret_cast<__half2*>(out + i)     = a;
    *reinterpret_cast<__half2*>(out + i + 2) = b;
}

// ---------------- fp16 single-pass tensor-core GEMM --------------------------
// C = act(alpha*(A @ B^T + bias'));  bias'[c] = (bias2 && c>=nsplit) ?
// bias2[c-nsplit] : bias[c].  A [M,K] fp16, B [N,K] fp16.
// BM=BN=128, BK=32; 4 warps x (64x64); 4-stage cp.async; single sync/iter.
#define LDSH 40                      // smem row stride in halves (80B, conflict-free)
#define TILE_B (128 * LDSH * 2)      // 10240B per tile
#define STAGE_B (2 * TILE_B)         // 20480B per stage (A, B)
#define NSTAGE 4
#define GEMM_SMEM (NSTAGE * STAGE_B) // 81920B

template <int RELU, int HOUT>
__global__ __launch_bounds__(128, 2)
void tc_gemm(const __half* __restrict__ A, const __half* __restrict__ B,
             const float* __restrict__ bias, const float* __restrict__ bias2,
             int nsplit,
             float* __restrict__ Cf, __half* __restrict__ Ch,
             int M, int N, int K, float alpha)
{
    extern __shared__ __half sm[];
    const uint32_t sb = smem_u32(sm);
    const int tid = threadIdx.x, wid = tid >> 5, lane = tid & 31;
    const int wm = wid & 1, wn = wid >> 1;
    const int m0 = blockIdx.y * 128, n0 = blockIdx.x * 128;
    const int nst = K >> 5;

    auto load_stage = [&](int s, int buf) {
        const int k0 = s << 5;
        const uint32_t d0 = sb + buf * STAGE_B;
        #pragma unroll
        for (int i = 0; i < 8; i++) {
            const int isA = (i < 4);
            const int c = (i & 3) * 128 + tid;
            const int row = c >> 2, part = c & 3;
            const __half* src = (isA ? A + (size_t)(m0 + row) * K
                                     : B + (size_t)(n0 + row) * K) + k0 + part * 8;
            const uint32_t dst = d0 + (isA ? 0 : TILE_B) + row * (LDSH * 2) + part * 16;
            CP16(dst, src);
        }
        CP_COMMIT();
    };

    float acc[4][8][4];
    #pragma unroll
    for (int i = 0; i < 4; i++)
        #pragma unroll
        for (int j = 0; j < 8; j++)
            #pragma unroll
            for (int q = 0; q < 4; q++) acc[i][j][q] = 0.f;

    load_stage(0, 0);
    load_stage(1, 1);
    load_stage(2, 2);

    const int a_r = (lane & 15), a_c8 = (lane >> 4) * 8;
    const int b_r = ((lane >> 4) & 1) * 8 + (lane & 7);
    const int b_c8 = ((lane >> 3) & 1) * 8;

    int buf = 0;
    #pragma unroll 1
    for (int s = 0; s < nst; s++) {
        CP_WAIT(2);
        __syncthreads();
        const int pb = (buf + 3) & 3;
        if (s + 3 < nst) load_stage(s + 3, pb); else CP_COMMIT();

        const uint32_t ab = sb + buf * STAGE_B;
        const uint32_t bb = ab + TILE_B;

        uint32_t fA[2][4][4], fB[2][4][4];
        #pragma unroll
        for (int ks = 0; ks < 2; ks++) {
            const int kh = ks * 16;
            #pragma unroll
            for (int i = 0; i < 4; i++) {
                const uint32_t off = ((wm * 64 + i * 16 + a_r) * LDSH + kh + a_c8) * 2;
                LDSM4(fA[ks][i], ab + off);
            }
            #pragma unroll
            for (int j = 0; j < 4; j++) {
                const uint32_t off = ((wn * 64 + j * 16 + b_r) * LDSH + kh + b_c8) * 2;
                LDSM4(fB[ks][j], bb + off);
            }
        }
        #pragma unroll
        for (int ks = 0; ks < 2; ks++) {
            #pragma unroll
            for (int n = 0; n < 8; n++) {
                const int j = n >> 1, h = (n & 1) * 2;
                const uint32_t b0 = fB[ks][j][h], b1 = fB[ks][j][h + 1];
                #pragma unroll
                for (int i = 0; i < 4; i++)
                    MMA_F16(acc[i][n], fA[ks][i], b0, b1);
            }
        }
        buf = (buf + 1) & 3;
    }

    // ---- epilogue ----
    const int row0 = m0 + wm * 64 + (lane >> 2);
    const int col0 = n0 + wn * 64 + (lane & 3) * 2;
    #pragma unroll
    for (int i = 0; i < 4; i++) {
        #pragma unroll
        for (int j = 0; j < 8; j++) {
            const int r = row0 + i * 16;
            const int c = col0 + j * 8;
            const float b0 = (bias2 && c >= nsplit) ? bias2[c - nsplit] : bias[c];
            const float b1 = (bias2 && c + 1 >= nsplit) ? bias2[c + 1 - nsplit] : bias[c + 1];
            float v0 = alpha * (acc[i][j][0] + b0);
            float v1 = alpha * (acc[i][j][1] + b1);
            float v2 = alpha * (acc[i][j][2] + b0);
            float v3 = alpha * (acc[i][j][3] + b1);
            if (RELU) {
                v0 = fmaxf(v0, 0.f); v1 = fmaxf(v1, 0.f);
                v2 = fmaxf(v2, 0.f); v3 = fmaxf(v3, 0.f);
            }
            if (!HOUT) {
                *reinterpret_cast<float2*>(Cf + (size_t)r * N + c)       = make_float2(v0, v1);
                *reinterpret_cast<float2*>(Cf + (size_t)(r + 8) * N + c) = make_float2(v2, v3);
            } else {
                *reinterpret_cast<__half2*>(Ch + (size_t)r * N + c) =
                    __half2(__float2half(v0), __float2half(v1));
                *reinterpret_cast<__half2*>(Ch + (size_t)(r + 8) * N + c) =
                    __half2(__float2half(v2), __float2half(v3));
            }
        }
    }
}

// ---------------- LayerNorm over D=768 ---------------------------------------
// mode 0: x = 2*a32[row]; mode 1: x = a16 + r32[row%G]; mode 2: x = a16 + r16[row]
__global__ __launch_bounds__(256)
void ln_kernel(const float* __restrict__ a32, const __half* __restrict__ a16,
               const float* __restrict__ r32, const __half* __restrict__ r16,
               const float* __restrict__ gamma, const float* __restrict__ beta,
               float* __restrict__ out, __half* __restrict__ oh, int mode)
{
    const int row = blockIdx.x;
    const int t = threadIdx.x;

    float x[3];
    #pragma unroll
    for (int j = 0; j < 3; j++) {
        const int idx = t + j * 256;
        float val;
        if (mode == 0) {
            val = 2.f * a32[(size_t)row * DD + idx];
        } else {
            val = __half2float(a16[(size_t)row * DD + idx]);
            if (mode == 1) val += r32[(size_t)(row & (GG - 1)) * DD + idx];
            else           val += __half2float(r16[(size_t)row * DD + idx]);
        }
        x[j] = val;
    }
    float s1 = x[0] + x[1] + x[2];
    float s2 = x[0] * x[0] + x[1] * x[1] + x[2] * x[2];
    #pragma unroll
    for (int off = 16; off; off >>= 1) {
        s1 += __shfl_xor_sync(0xffffffffu, s1, off);
        s2 += __shfl_xor_sync(0xffffffffu, s2, off);
    }
    __shared__ float sh1[8], sh2[8];
    const int w = t >> 5, lane = t & 31;
    if (lane == 0) { sh1[w] = s1; sh2[w] = s2; }
    __syncthreads();
    float S1 = 0.f, S2 = 0.f;
    #pragma unroll
    for (int i = 0; i < 8; i++) { S1 += sh1[i]; S2 += sh2[i]; }
    const float mean = S1 * (1.f / (float)DD);
    const float var  = S2 * (1.f / (float)DD) - mean * mean;
    const float rstd = rsqrtf(var + 1e-5f);

    #pragma unroll
    for (int j = 0; j < 3; j++) {
        const int idx = t + j * 256;
        const float v = (x[j] - mean) * rstd * gamma[idx] + beta[idx];
        if (out) out[(size_t)row * DD + idx] = v;
        if (oh) oh[(size_t)row * DD + idx] = __float2half(v);
    }
}

// ---------------- fused cross-attention (fp16 kv concat), fp16 output --------
__global__ __launch_bounds__(256)
void attn_kernel(const float* __restrict__ q, const __half* __restrict__ kv,
                 __half* __restrict__ oh)
{
    __shared__ float ks[NN][HD];
    __shared__ float vs[NN][HD];
    const int h = blockIdx.x, b = blockIdx.y;
    const int t = threadIdx.x;

    for (int i = t; i < NN * HD; i += 256) {
        const int n = i / HD, d = i % HD;
        const size_t gi = ((size_t)(b * NN + n)) * DKV + h * HD + d;
        ks[n][d] = __half2float(kv[gi]);
        vs[n][d] = __half2float(kv[gi + DD]);
    }
    __syncthreads();

    const int g = t;
    float4 qv[HD / 4];
    const float4* qp = reinterpret_cast<const float4*>(q + (size_t)g * DD + h * HD);
    #pragma unroll
    for (int i = 0; i < HD / 4; i++) qv[i] = qp[i];

    float s[NN];
    #pragma unroll 7
    for (int n = 0; n < NN; n++) {
        const float4* kp = reinterpret_cast<const float4*>(ks[n]);
        float acc = 0.f;
        #pragma unroll
        for (int i = 0; i < HD / 4; i++) {
            float4 kk = kp[i];
            acc += qv[i].x * kk.x + qv[i].y * kk.y + qv[i].z * kk.z + qv[i].w * kk.w;
        }
        s[n] = acc;
    }
    float m = -1e30f;
    #pragma unroll
    for (int n = 0; n < NN; n++) m = fmaxf(m, s[n]);
    float sum = 0.f;
    #pragma unroll
    for (int n = 0; n < NN; n++) { s[n] = __expf(s[n] - m); sum += s[n]; }
    const float inv = 1.f / sum;

    const size_t ob = ((size_t)(b * GG + g)) * DD + h * HD;
    #pragma unroll
    for (int d4 = 0; d4 < HD / 4; d4++) {
        float4 acc = {0.f, 0.f, 0.f, 0.f};
        #pragma unroll 7
        for (int n = 0; n < NN; n++) {
            const float p = s[n];
            float4 vv = *reinterpret_cast<const float4*>(&vs[n][d4 * 4]);
            acc.x += p * vv.x; acc.y += p * vv.y; acc.z += p * vv.z; acc.w += p * vv.w;
        }
        acc.x *= inv; acc.y *= inv; acc.z *= inv; acc.w *= inv;
        *reinterpret_cast<__half2*>(oh + ob + d4 * 4) =
            __half2(__float2half(acc.x), __float2half(acc.y));
        *reinterpret_cast<__half2*>(oh + ob + d4 * 4 + 2) =
            __half2(__float2half(acc.z), __float2half(acc.w));
    }
}

// ---------------- GroupFC on tensor cores ------------------------------------
#define GF_A_B (128 * LDSH * 2)          // 10240B
#define GF_B_B (64 * LDSH * 2)           // 5120B
#define GF_STAGE (GF_A_B + GF_B_B)       // 15360B
#define GF_SMEM (2 * GF_STAGE)           // 30720B

__global__ __launch_bounds__(128, 2)
void groupfc_tc(const __half* __restrict__ h, const __half* __restrict__ Wt,
                const float* __restrict__ bg, float* __restrict__ out)
{
    extern __shared__ __half sm[];
    const uint32_t sb = smem_u32(sm);
    const int g = blockIdx.x;
    const int tid = threadIdx.x, wid = tid >> 5, lane = tid & 31;

    auto load_stage = [&](int s, int buf) {
        const int k0 = s << 5;
        const uint32_t d0 = sb + buf * GF_STAGE;
        #pragma unroll
        for (int i = 0; i < 4; i++) {
            const int c = i * 128 + tid;
            const int row = c >> 2, part = c & 3;
            const __half* src = h + ((size_t)(row * GG + g)) * DD + k0 + part * 8;
            CP16(d0 + row * (LDSH * 2) + part * 16, src);
        }
        #pragma unroll
        for (int i = 0; i < 2; i++) {
            const int c = i * 128 + tid;
            const int row = c >> 2, part = c & 3;
            const __half* src = Wt + (size_t)g * 64 * DD + (size_t)row * DD + k0 + part * 8;
            CP16(d0 + GF_A_B + row * (LDSH * 2) + part * 16, src);
        }
        CP_COMMIT();
    };

    float acc[2][8][4];
    #pragma unroll
    for (int i = 0; i < 2; i++)
        #pragma unroll
        for (int j = 0; j < 8; j++)
            #pragma unroll
            for (int q = 0; q < 4; q++) acc[i][j][q] = 0.f;

    load_stage(0, 0);

    const int a_r = (lane & 15), a_c8 = (lane >> 4) * 8;
    const int b_r = ((lane >> 4) & 1) * 8 + (lane & 7);
    const int b_c8 = ((lane >> 3) & 1) * 8;
    const int nst = DD >> 5;

    #pragma unroll 1
    for (int s = 0; s < nst; s++) {
        if (s + 1 < nst) load_stage(s + 1, (s + 1) & 1); else CP_COMMIT();
        CP_WAIT(1);
        __syncthreads();
        const uint32_t ab = sb + (s & 1) * GF_STAGE;
        const uint32_t bb = ab + GF_A_B;

        #pragma unroll
        for (int ks = 0; ks < 2; ks++) {
            const int kh = ks * 16;
            uint32_t fA[2][4], fB[4][4];
            #pragma unroll
            for (int i = 0; i < 2; i++) {
                const uint32_t off = ((wid * 32 + i * 16 + a_r) * LDSH + kh + a_c8) * 2;
                LDSM4(fA[i], ab + off);
            }
            #pragma unroll
            for (int j = 0; j < 4; j++) {
                const uint32_t off = ((j * 16 + b_r) * LDSH + kh + b_c8) * 2;
                LDSM4(fB[j], bb + off);
            }
            #pragma unroll
            for (int n = 0; n < 8; n++) {
                const int j = n >> 1, hh = (n & 1) * 2;
                const uint32_t b0 = fB[j][hh], b1 = fB[j][hh + 1];
                #pragma unroll
                for (int i = 0; i < 2; i++)
                    MMA_F16(acc[i][n], fA[i], b0, b1);
            }
        }
        __syncthreads();
    }

    const int row0 = wid * 32 + (lane >> 2);
    const int col0 = (lane & 3) * 2;
    #pragma unroll
    for (int i = 0; i < 2; i++) {
        #pragma unroll
        for (int j = 0; j < 8; j++) {
            const int r0 = row0 + i * 16;
            const int f0 = col0 + j * 8;
            #pragma unroll
            for (int e = 0; e < 2; e++) {
                const int f = f0 + e;
                const int c = g * DUP + f;
                if (f < DUP && c < NCLS) {
                    out[(size_t)r0 * NCLS + c]       = acc[i][j][0 + e] + bg[c];
                    out[(size_t)(r0 + 8) * NCLS + c] = acc[i][j][2 + e] + bg[c];
                }
            }
        }
    }
}

// ---------------- launch -----------------------------------------------------
static float* sym(const void* s) { void* p = nullptr; cudaGetSymbolAddress(&p, s); return (float*)p; }
static __half* symh(const void* s) { void* p = nullptr; cudaGetSymbolAddress(&p, s); return (__half*)p; }

extern "C" void kernel_launch(void* const* d_in, const int* in_sizes, int n_in,
                              void* d_out, int out_size)
{
    (void)in_sizes; (void)n_in; (void)out_size;
    const float* x      = (const float*)d_in[0];
    const float* We     = (const float*)d_in[1];
    const float* be     = (const float*)d_in[2];
    const float* query  = (const float*)d_in[3];
    const float* Wq     = (const float*)d_in[4];
    const float* bq     = (const float*)d_in[5];
    const float* Wk     = (const float*)d_in[6];
    const float* bk     = (const float*)d_in[7];
    const float* Wv     = (const float*)d_in[8];
    const float* bv     = (const float*)d_in[9];
    const float* Wo     = (const float*)d_in[10];
    const float* bo     = (const float*)d_in[11];
    const float* g1     = (const float*)d_in[12];
    const float* beta1  = (const float*)d_in[13];
    const float* g2     = (const float*)d_in[14];
    const float* beta2  = (const float*)d_in[15];
    const float* g3     = (const float*)d_in[16];
    const float* beta3  = (const float*)d_in[17];
    const float* W1     = (const float*)d_in[18];
    const float* b1     = (const float*)d_in[19];
    const float* W2     = (const float*)d_in[20];
    const float* b2     = (const float*)d_in[21];
    const float* Wg     = (const float*)d_in[22];
    const float* bg     = (const float*)d_in[23];
    float* out = (float*)d_out;

    float *p_t1 = sym(g_t1), *p_q = sym(g_q);
    __half *p_xh = symh(g_xh), *p_mh = symh(g_mh), *p_t1h = symh(g_t1h);
    __half *p_kvh = symh(g_kvh), *p_aoh = symh(g_aoh), *p_oph = symh(g_oph);
    __half *p_t2h = symh(g_t2h), *p_ffh = symh(g_ffh), *p_f2h = symh(g_f2h);
    __half *p_hh = symh(g_hh);
    __half *pWe = symh(tWe), *pWq = symh(tWq), *pWkv = symh(tWkv);
    __half *pWo = symh(tWo), *pW1 = symh(tW1), *pW2 = symh(tW2), *pWg = symh(tWg);

    cudaFuncSetAttribute(tc_gemm<0, 0>, cudaFuncAttributeMaxDynamicSharedMemorySize, GEMM_SMEM);
    cudaFuncSetAttribute(tc_gemm<0, 1>, cudaFuncAttributeMaxDynamicSharedMemorySize, GEMM_SMEM);
    cudaFuncSetAttribute(tc_gemm<1, 1>, cudaFuncAttributeMaxDynamicSharedMemorySize, GEMM_SMEM);
    cudaFuncSetAttribute(groupfc_tc, cudaFuncAttributeMaxDynamicSharedMemorySize, GF_SMEM);

    const float qscale = 0.10206207261596577f;  // 1/sqrt(96)

    // Side stream for independent prep (fork/join pattern; capture-legal).
    cudaStream_t s1;
    cudaStreamCreateWithFlags(&s1, cudaStreamNonBlocking);
    cudaEvent_t eStart, eWq, eSide;
    cudaEventCreateWithFlags(&eStart, cudaEventDisableTiming);
    cudaEventCreateWithFlags(&eWq,    cudaEventDisableTiming);
    cudaEventCreateWithFlags(&eSide,  cudaEventDisableTiming);

    // ---- fork: side stream handles W1/W2/Wg transposes + q-chain ----
    cudaEventRecord(eStart, 0);
    cudaStreamWaitEvent(s1, eStart, 0);

    // side stream: input-only work first
    ln_kernel<<<GG, 256, 0, s1>>>(query, nullptr, nullptr, nullptr,
                                  g1, beta1, p_t1, p_t1h, 0);
    transpose_half<<<dim3(FF / 32, DD / 32), 256, 0, s1>>>(W1, pW1, DD, FF);
    transpose_half<<<dim3(DD / 32, FF / 32), 256, 0, s1>>>(W2, pW2, FF, DD);
    transpose_wg<<<dim3(NGRP, DD / 128), 256, 0, s1>>>(Wg, pWg);

    // main stream: transposes + convert feeding the early GEMMs
    transpose4_half<<<dim3(DD / 32, DD / 32, 4), 256>>>(
        Wq, pWq, Wk, pWkv, Wv, pWkv + (size_t)DD * DD, Wo, pWo);
    cudaEventRecord(eWq, 0);                      // tWq ready for side q-gemm
    transpose_half<<<dim3(DD / 32, CIN / 32), 256>>>(We, pWe, CIN, DD);
    convert_half<<<(BB * NN * CIN) / 1024, 256>>>(x, p_xh);

    // side stream: q = (t1@Wq + bq)/sqrt(96)   (needs tWq)
    cudaStreamWaitEvent(s1, eWq, 0);
    tc_gemm<0, 0><<<dim3(DD / 128, GG / 128), 128, GEMM_SMEM, s1>>>(
        p_t1h, pWq, bq, nullptr, 0, p_q, nullptr, GG, DD, DD, qscale);
    cudaEventRecord(eSide, s1);

    // main stream: embed + fused K|V (dual bias replaces concat kernel)
    tc_gemm<1, 1><<<dim3(DD / 128, (BB * NN) / 128), 128, GEMM_SMEM>>>(
        p_xh, pWe, be, nullptr, 0, nullptr, p_mh, BB * NN, DD, CIN, 1.f);
    tc_gemm<0, 1><<<dim3(DKV / 128, (BB * NN) / 128), 128, GEMM_SMEM>>>(
        p_mh, pWkv, bk, bv, DD, nullptr, p_kvh, BB * NN, DKV, DD, 1.f);

    // ---- join: attention needs q (side) + kv (main); W1/W2/Wg also joined ----
    cudaStreamWaitEvent(0, eSide, 0);
    attn_kernel<<<dim3(HH, BB), 256>>>(p_q, p_kvh, p_aoh);

    // output projection (fp16) + residual LN -> t2h (fp16 only)
    tc_gemm<0, 1><<<dim3(DD / 128, (BB * GG) / 128), 128, GEMM_SMEM>>>(
        p_aoh, pWo, bo, nullptr, 0, nullptr, p_oph, BB * GG, DD, DD, 1.f);
    ln_kernel<<<BB * GG, 256>>>(nullptr, p_oph, p_t1, nullptr, g2, beta2,
                                nullptr, p_t2h, 1);

    // FFN: ff = relu(t2@W1+b1) -> fp16; ffn2 = ff@W2+b2 -> fp16
    tc_gemm<1, 1><<<dim3(FF / 128, (BB * GG) / 128), 128, GEMM_SMEM>>>(
        p_t2h, pW1, b1, nullptr, 0, nullptr, p_ffh, BB * GG, FF, DD, 1.f);
    tc_gemm<0, 1><<<dim3(DD / 128, (BB * GG) / 128), 128, GEMM_SMEM>>>(
        p_ffh, pW2, b2, nullptr, 0, nullptr, p_f2h, BB * GG, DD, FF, 1.f);
    // h = LN(t2h + ffn2) -> fp16
    ln_kernel<<<BB * GG, 256>>>(nullptr, p_f2h, nullptr, p_t2h, g3, beta3,
                                nullptr, p_hh, 2);

    // GroupFC on tensor cores
    groupfc_tc<<<NGRP, 128, GF_SMEM>>>(p_hh, pWg, bg, out);
}